// round 5
// baseline (speedup 1.0000x reference)
#include <cuda_runtime.h>
#include <math.h>
#include <stdint.h>

// ---------------- problem constants ----------------
#define Bn   4
#define Sn   512
#define Dm   1024
#define Hn   16
#define HD   64
#define En   8
#define FF   2048
#define Ln   2
#define VT   32000
#define TOK  (Bn*Sn)      // 2048 tokens

#define KT   16           // K-tile
#define AST  20           // [m][k] smem stride (u32): g*20+t4 distinct mod 32
#define BST  136          // [k][n] smem stride (u32): t4*8+g distinct mod 32

#define ASZ  (128*AST)            // 2560 u32
#define BSZ0 (KT*BST)             // 2176 u32
#define BSZ1 (128*AST)            // 2560 u32
#define STG0 (2*ASZ + 2*BSZ0)     // u32 per stage, BT=0
#define STG1 (2*ASZ + 2*BSZ1)     // u32 per stage, BT=1
#define SMEM0_BYTES (2*STG0*4)    // 75776
#define SMEM1_BYTES (2*STG1*4)    // 81920

// ---------------- device scratch (no allocations allowed) ----------------
__device__ float    g_x[TOK*Dm];
__device__ float    g_y[TOK*Dm];
__device__ uint32_t g_xh[TOK*Dm], g_xl[TOK*Dm];
__device__ uint32_t g_yh[TOK*Dm], g_yl[TOK*Dm];
__device__ float    g_lin0[TOK*Dm];
__device__ float    g_lin1[TOK*Dm];
__device__ float    g_lin2[TOK*Dm];
__device__ uint32_t g_qh[TOK*Dm], g_ql[TOK*Dm];
__device__ uint32_t g_kh[TOK*Dm], g_kl[TOK*Dm];
__device__ uint32_t g_vh[TOK*Dm], g_vl[TOK*Dm];
__device__ float    g_sc[(size_t)Bn*Hn*Sn*Sn];                 // fp32 scores (QK out)
__device__ uint32_t g_sch[(size_t)Bn*Hn*Sn*Sn], g_scl[(size_t)Bn*Hn*Sn*Sn];
__device__ float    g_att[TOK*Dm];
__device__ uint32_t g_atth[TOK*Dm], g_attl[TOK*Dm];            // att_t hi/lo
__device__ float    g_proj[TOK*Dm];
__device__ uint32_t g_h1h[(size_t)En*TOK*FF], g_h1l[(size_t)En*TOK*FF];
__device__ float    g_moe0[TOK*Dm];
__device__ float    g_moe1[TOK*Dm];
__device__ float    g_gate[TOK*En];
__device__ float    g_topw[TOK*2];
__device__ int      g_list[En*TOK];
__device__ int      g_cnt[En];
__device__ float    g_cos[Sn*HD];
__device__ float    g_sin[Sn*HD];
__device__ uint32_t g_wsh[33554432], g_wsl[33554432];          // weight split scratch (128MB ea)

// ---------------- tf32 / cp.async helpers ----------------
__device__ __forceinline__ uint32_t f2tf(float f) {
    uint32_t r;
    asm("cvt.rna.tf32.f32 %0, %1;" : "=r"(r) : "f"(f));
    return r;
}
__device__ __forceinline__ void sp(float v, uint32_t& h, uint32_t& l) {
    h = f2tf(v);
    l = f2tf(v - __uint_as_float(h));
}
__device__ __forceinline__ uint32_t smem_u32(const void* p) {
    return (uint32_t)__cvta_generic_to_shared(p);
}
__device__ __forceinline__ void cp16(uint32_t dst, const void* src) {
    asm volatile("cp.async.cg.shared.global [%0], [%1], 16;" :: "r"(dst), "l"(src));
}
__device__ __forceinline__ void cp16z(uint32_t dst, const void* src, bool ok) {
    int sz = ok ? 16 : 0;
    asm volatile("cp.async.cg.shared.global [%0], [%1], 16, %2;" :: "r"(dst), "l"(src), "r"(sz));
}
#define CP_COMMIT() asm volatile("cp.async.commit_group;")
#define CP_WAIT1()  asm volatile("cp.async.wait_group 1;")
#define CP_WAIT0()  asm volatile("cp.async.wait_group 0;")

__device__ __forceinline__ void mma_tf32(float* c, const uint32_t* a, const uint32_t* b) {
    asm volatile(
        "mma.sync.aligned.m16n8k8.row.col.f32.tf32.tf32.f32 "
        "{%0,%1,%2,%3}, {%4,%5,%6,%7}, {%8,%9}, {%0,%1,%2,%3};"
        : "+f"(c[0]), "+f"(c[1]), "+f"(c[2]), "+f"(c[3])
        : "r"(a[0]), "r"(a[1]), "r"(a[2]), "r"(a[3]), "r"(b[0]), "r"(b[1]));
}

// compute over one k-tile; BIDX0/BIDX1 are B smem index expressions in (kr, nb)
#define MMA_COMPUTE_HL(BIDX0, BIDX1)                                               \
  { const int moff = wm * 64, noff = wn * 32;                                      \
    _Pragma("unroll")                                                              \
    for (int ks = 0; ks < 2; ks++) {                                               \
        const int kr = ks * 8 + t4;                                                \
        uint32_t afH[4][4], afL[4][4], bfH[4][2], bfL[4][2];                       \
        _Pragma("unroll")                                                          \
        for (int mt = 0; mt < 4; mt++) {                                           \
            int mb = moff + mt * 16 + g;                                           \
            afH[mt][0] = Ah_s[mb * AST + kr];                                      \
            afL[mt][0] = Al_s[mb * AST + kr];                                      \
            afH[mt][1] = Ah_s[(mb + 8) * AST + kr];                                \
            afL[mt][1] = Al_s[(mb + 8) * AST + kr];                                \
            afH[mt][2] = Ah_s[mb * AST + kr + 4];                                  \
            afL[mt][2] = Al_s[mb * AST + kr + 4];                                  \
            afH[mt][3] = Ah_s[(mb + 8) * AST + kr + 4];                            \
            afL[mt][3] = Al_s[(mb + 8) * AST + kr + 4];                            \
        }                                                                          \
        _Pragma("unroll")                                                          \
        for (int nt = 0; nt < 4; nt++) {                                           \
            int nb = noff + nt * 8 + g;                                            \
            bfH[nt][0] = Bh_s[BIDX0]; bfL[nt][0] = Bl_s[BIDX0];                    \
            bfH[nt][1] = Bh_s[BIDX1]; bfL[nt][1] = Bl_s[BIDX1];                    \
        }                                                                          \
        _Pragma("unroll")                                                          \
        for (int mt = 0; mt < 4; mt++)                                             \
            _Pragma("unroll")                                                      \
            for (int nt = 0; nt < 4; nt++) {                                       \
                mma_tf32(acc[mt][nt], afH[mt], bfL[nt]);                           \
                mma_tf32(acc[mt][nt], afL[mt], bfH[nt]);                           \
                mma_tf32(acc[mt][nt], afH[mt], bfH[nt]);                           \
            }                                                                      \
    } }

// =====================================================================
// hi/lo 3xTF32 GEMM: C = alpha*(Ahl@Bhl) + bias (opt relu)
// Operands pre-split to tf32 hi/lo u32 arrays. Dynamic smem, 2-stage cp.async.
// BT=0: B [K,N].  BT=1: B [N,K] (NT).  M%128==0, K%16==0, N guarded.
// =====================================================================
template<int BT>
__global__ void __launch_bounds__(256) mma_gemm_hl(
    const uint32_t* __restrict__ Ah, const uint32_t* __restrict__ Al,
    const uint32_t* __restrict__ Bh, const uint32_t* __restrict__ Bl,
    const float* __restrict__ bias, float* __restrict__ C,
    int M, int N, int K, int relu, float alpha,
    long long sA, long long sB, long long sC)
{
    constexpr int BSZ = BT ? BSZ1 : BSZ0;
    constexpr int STG = 2 * ASZ + 2 * BSZ;
    extern __shared__ uint32_t dsm[];
    Ah += (long long)blockIdx.z * sA;  Al += (long long)blockIdx.z * sA;
    Bh += (long long)blockIdx.z * sB;  Bl += (long long)blockIdx.z * sB;
    C  += (long long)blockIdx.z * sC;
    const int tid  = threadIdx.x;
    const int lane = tid & 31;
    const int warp = tid >> 5;
    const int wm = warp >> 2, wn = warp & 3;
    const int g  = lane >> 2, t4 = lane & 3;
    const int bm = blockIdx.y * 128, bn = blockIdx.x * 128;

    float acc[4][4][4];
#pragma unroll
    for (int i = 0; i < 4; i++)
#pragma unroll
        for (int j = 0; j < 4; j++)
#pragma unroll
            for (int q = 0; q < 4; q++) acc[i][j][q] = 0.f;

    auto issue_tile = [&](int kt, int st) {
        uint32_t* Ah_d = dsm + st * STG;
        uint32_t* Al_d = Ah_d + ASZ;
        uint32_t* Bh_d = Al_d + ASZ;
        uint32_t* Bl_d = Bh_d + BSZ;
        long long k0 = (long long)kt * KT;
#pragma unroll
        for (int i = 0; i < 2; i++) {
            int c = tid + i * 256;
            int m = c >> 2, cq = c & 3;
            long long go = (long long)(bm + m) * K + k0 + cq * 4;
            cp16(smem_u32(&Ah_d[m * AST + cq * 4]), Ah + go);
            cp16(smem_u32(&Al_d[m * AST + cq * 4]), Al + go);
        }
        if (BT == 0) {
#pragma unroll
            for (int i = 0; i < 2; i++) {
                int c = tid + i * 256;
                int kk = c >> 5, nq = c & 31;
                int gc = bn + nq * 4;
                long long go = (long long)(k0 + kk) * N + gc;
                cp16z(smem_u32(&Bh_d[kk * BST + nq * 4]), Bh + go, gc < N);
                cp16z(smem_u32(&Bl_d[kk * BST + nq * 4]), Bl + go, gc < N);
            }
        } else {
#pragma unroll
            for (int i = 0; i < 2; i++) {
                int c = tid + i * 256;
                int n = c >> 2, cq = c & 3;
                long long go = (long long)(bn + n) * K + k0 + cq * 4;
                cp16(smem_u32(&Bh_d[n * AST + cq * 4]), Bh + go);
                cp16(smem_u32(&Bl_d[n * AST + cq * 4]), Bl + go);
            }
        }
        CP_COMMIT();
    };

    const int nk = K / KT;
    issue_tile(0, 0);
    for (int kt = 0; kt < nk; kt++) {
        if (kt + 1 < nk) { issue_tile(kt + 1, (kt + 1) & 1); CP_WAIT1(); }
        else             { CP_WAIT0(); }
        __syncthreads();
        const uint32_t* Ah_s = dsm + (kt & 1) * STG;
        const uint32_t* Al_s = Ah_s + ASZ;
        const uint32_t* Bh_s = Al_s + ASZ;
        const uint32_t* Bl_s = Bh_s + BSZ;
        if (BT == 0) {
            MMA_COMPUTE_HL(kr * BST + nb, (kr + 4) * BST + nb)
        } else {
            MMA_COMPUTE_HL(nb * AST + kr, nb * AST + kr + 4)
        }
        __syncthreads();
    }

    // ---- epilogue ----
#pragma unroll
    for (int mt = 0; mt < 4; mt++) {
        int m0 = bm + wm * 64 + mt * 16 + g;
#pragma unroll
        for (int nt = 0; nt < 4; nt++) {
            int n0 = bn + wn * 32 + nt * 8 + t4 * 2;
            if (n0 < N) {
                float b0v = bias ? bias[n0] : 0.f;
                float b1v = bias ? bias[n0 + 1] : 0.f;
                float o0 = acc[mt][nt][0] * alpha + b0v;
                float o1 = acc[mt][nt][1] * alpha + b1v;
                float o2 = acc[mt][nt][2] * alpha + b0v;
                float o3 = acc[mt][nt][3] * alpha + b1v;
                if (relu) {
                    o0 = fmaxf(o0, 0.f); o1 = fmaxf(o1, 0.f);
                    o2 = fmaxf(o2, 0.f); o3 = fmaxf(o3, 0.f);
                }
                C[(long long)m0 * N + n0] = o0;
                C[(long long)m0 * N + n0 + 1] = o1;
                C[(long long)(m0 + 8) * N + n0] = o2;
                C[(long long)(m0 + 8) * N + n0 + 1] = o3;
            }
        }
    }
}

// =====================================================================
// MoE GEMM 1 (z=expert): H1hl[e] = split(relu(Xhl[toks_e] @ W1hl[e] + b1[e]))
// =====================================================================
__global__ void __launch_bounds__(256) moe_mma1_hl(
    const uint32_t* __restrict__ Xh, const uint32_t* __restrict__ Xl,
    const uint32_t* __restrict__ Wh, const uint32_t* __restrict__ Wl,
    const float* __restrict__ b1,
    uint32_t* __restrict__ H1h, uint32_t* __restrict__ H1l,
    const int* __restrict__ list, const int* __restrict__ cnt)
{
    constexpr int STG = 2 * ASZ + 2 * BSZ0;
    extern __shared__ uint32_t dsm[];
    __shared__ int toks[128];
    const int e = blockIdx.z;
    const int nrows = cnt[e];
    const int bm = blockIdx.y * 128, bn = blockIdx.x * 128;
    if (bm >= nrows) return;
    const uint32_t* __restrict__ Whe = Wh + (long long)e * Dm * FF;
    const uint32_t* __restrict__ Wle = Wl + (long long)e * Dm * FF;
    const float* __restrict__ bias = b1 + e * FF;
    uint32_t* __restrict__ Hh = H1h + (size_t)e * TOK * FF;
    uint32_t* __restrict__ Hl = H1l + (size_t)e * TOK * FF;
    const int* __restrict__ lst = list + e * TOK;

    const int tid = threadIdx.x;
    const int lane = tid & 31, warp = tid >> 5;
    const int wm = warp >> 2, wn = warp & 3;
    const int g = lane >> 2, t4 = lane & 3;
    if (tid < 128) {
        int gr = bm + tid;
        toks[tid] = (gr < nrows) ? (lst[gr] >> 1) : 0;
    }
    __syncthreads();

    float acc[4][4][4];
#pragma unroll
    for (int i = 0; i < 4; i++)
#pragma unroll
        for (int j = 0; j < 4; j++)
#pragma unroll
            for (int q = 0; q < 4; q++) acc[i][j][q] = 0.f;

    auto issue_tile = [&](int kt, int st) {
        uint32_t* Ah_d = dsm + st * STG;
        uint32_t* Al_d = Ah_d + ASZ;
        uint32_t* Bh_d = Al_d + ASZ;
        uint32_t* Bl_d = Bh_d + BSZ0;
        long long k0 = (long long)kt * KT;
#pragma unroll
        for (int i = 0; i < 2; i++) {
            int c = tid + i * 256;
            int m = c >> 2, cq = c & 3;
            long long go = (long long)toks[m] * Dm + k0 + cq * 4;
            cp16(smem_u32(&Ah_d[m * AST + cq * 4]), Xh + go);
            cp16(smem_u32(&Al_d[m * AST + cq * 4]), Xl + go);
        }
#pragma unroll
        for (int i = 0; i < 2; i++) {
            int c = tid + i * 256;
            int kk = c >> 5, nq = c & 31;
            long long go = (long long)(k0 + kk) * FF + bn + nq * 4;
            cp16(smem_u32(&Bh_d[kk * BST + nq * 4]), Whe + go);
            cp16(smem_u32(&Bl_d[kk * BST + nq * 4]), Wle + go);
        }
        CP_COMMIT();
    };

    const int nk = Dm / KT;
    issue_tile(0, 0);
    for (int kt = 0; kt < nk; kt++) {
        if (kt + 1 < nk) { issue_tile(kt + 1, (kt + 1) & 1); CP_WAIT1(); }
        else             { CP_WAIT0(); }
        __syncthreads();
        const uint32_t* Ah_s = dsm + (kt & 1) * STG;
        const uint32_t* Al_s = Ah_s + ASZ;
        const uint32_t* Bh_s = Al_s + ASZ;
        const uint32_t* Bl_s = Bh_s + BSZ0;
        MMA_COMPUTE_HL(kr * BST + nb, (kr + 4) * BST + nb)
        __syncthreads();
    }

#pragma unroll
    for (int mt = 0; mt < 4; mt++) {
        int lr = wm * 64 + mt * 16 + g;
#pragma unroll
        for (int nt = 0; nt < 4; nt++) {
            int n0 = bn + wn * 32 + nt * 8 + t4 * 2;
            float b0v = bias[n0], b1v = bias[n0 + 1];
            if (bm + lr < nrows) {
                size_t o = (size_t)(bm + lr) * FF + n0;
                uint32_t h, l;
                sp(fmaxf(acc[mt][nt][0] + b0v, 0.f), h, l); Hh[o] = h; Hl[o] = l;
                sp(fmaxf(acc[mt][nt][1] + b1v, 0.f), h, l); Hh[o + 1] = h; Hl[o + 1] = l;
            }
            if (bm + lr + 8 < nrows) {
                size_t o = (size_t)(bm + lr + 8) * FF + n0;
                uint32_t h, l;
                sp(fmaxf(acc[mt][nt][2] + b0v, 0.f), h, l); Hh[o] = h; Hl[o] = l;
                sp(fmaxf(acc[mt][nt][3] + b1v, 0.f), h, l); Hh[o + 1] = h; Hl[o + 1] = l;
            }
        }
    }
}

// =====================================================================
// MoE GEMM 2 (z=expert, scatter): out_slot[token] = w * (H1hl[e] @ W2hl[e] + b2[e])
// =====================================================================
__global__ void __launch_bounds__(256) moe_mma2_hl(
    const uint32_t* __restrict__ H1h, const uint32_t* __restrict__ H1l,
    const uint32_t* __restrict__ Wh, const uint32_t* __restrict__ Wl,
    const float* __restrict__ b2,
    float* __restrict__ out0, float* __restrict__ out1,
    const float* __restrict__ topw,
    const int* __restrict__ list, const int* __restrict__ cnt)
{
    constexpr int STG = 2 * ASZ + 2 * BSZ0;
    extern __shared__ uint32_t dsm[];
    __shared__ int ents[128];
    const int e = blockIdx.z;
    const int nrows = cnt[e];
    const int bm = blockIdx.y * 128, bn = blockIdx.x * 128;
    if (bm >= nrows) return;
    const uint32_t* __restrict__ Whe = Wh + (long long)e * FF * Dm;
    const uint32_t* __restrict__ Wle = Wl + (long long)e * FF * Dm;
    const float* __restrict__ bias = b2 + e * Dm;
    const uint32_t* __restrict__ Hh = H1h + (size_t)e * TOK * FF;
    const uint32_t* __restrict__ Hl = H1l + (size_t)e * TOK * FF;
    const int* __restrict__ lst = list + e * TOK;

    const int tid = threadIdx.x;
    const int lane = tid & 31, warp = tid >> 5;
    const int wm = warp >> 2, wn = warp & 3;
    const int g = lane >> 2, t4 = lane & 3;
    if (tid < 128) {
        int gr = bm + tid;
        ents[tid] = (gr < nrows) ? lst[gr] : -1;
    }
    __syncthreads();

    float acc[4][4][4];
#pragma unroll
    for (int i = 0; i < 4; i++)
#pragma unroll
        for (int j = 0; j < 4; j++)
#pragma unroll
            for (int q = 0; q < 4; q++) acc[i][j][q] = 0.f;

    auto issue_tile = [&](int kt, int st) {
        uint32_t* Ah_d = dsm + st * STG;
        uint32_t* Al_d = Ah_d + ASZ;
        uint32_t* Bh_d = Al_d + ASZ;
        uint32_t* Bl_d = Bh_d + BSZ0;
        long long k0 = (long long)kt * KT;
#pragma unroll
        for (int i = 0; i < 2; i++) {
            int c = tid + i * 256;
            int m = c >> 2, cq = c & 3;
            size_t go = (size_t)(bm + m) * FF + k0 + cq * 4;
            cp16(smem_u32(&Ah_d[m * AST + cq * 4]), Hh + go);
            cp16(smem_u32(&Al_d[m * AST + cq * 4]), Hl + go);
        }
#pragma unroll
        for (int i = 0; i < 2; i++) {
            int c = tid + i * 256;
            int kk = c >> 5, nq = c & 31;
            long long go = (long long)(k0 + kk) * Dm + bn + nq * 4;
            cp16(smem_u32(&Bh_d[kk * BST + nq * 4]), Whe + go);
            cp16(smem_u32(&Bl_d[kk * BST + nq * 4]), Wle + go);
        }
        CP_COMMIT();
    };

    const int nk = FF / KT;
    issue_tile(0, 0);
    for (int kt = 0; kt < nk; kt++) {
        if (kt + 1 < nk) { issue_tile(kt + 1, (kt + 1) & 1); CP_WAIT1(); }
        else             { CP_WAIT0(); }
        __syncthreads();
        const uint32_t* Ah_s = dsm + (kt & 1) * STG;
        const uint32_t* Al_s = Ah_s + ASZ;
        const uint32_t* Bh_s = Al_s + ASZ;
        const uint32_t* Bl_s = Bh_s + BSZ0;
        MMA_COMPUTE_HL(kr * BST + nb, (kr + 4) * BST + nb)
        __syncthreads();
    }

#pragma unroll
    for (int mt = 0; mt < 4; mt++) {
        int lr = wm * 64 + mt * 16 + g;
        int e0 = ents[lr], e2 = ents[lr + 8];
#pragma unroll
        for (int nt = 0; nt < 4; nt++) {
            int n0 = bn + wn * 32 + nt * 8 + t4 * 2;
            float b0v = bias[n0], b1v = bias[n0 + 1];
            if (e0 >= 0) {
                float w = topw[e0];
                float* o = (e0 & 1) ? out1 : out0;
                long long t = (long long)(e0 >> 1) * Dm;
                o[t + n0]     = w * (acc[mt][nt][0] + b0v);
                o[t + n0 + 1] = w * (acc[mt][nt][1] + b1v);
            }
            if (e2 >= 0) {
                float w = topw[e2];
                float* o = (e2 & 1) ? out1 : out0;
                long long t = (long long)(e2 >> 1) * Dm;
                o[t + n0]     = w * (acc[mt][nt][2] + b0v);
                o[t + n0 + 1] = w * (acc[mt][nt][3] + b1v);
            }
        }
    }
}

// ---------------- fp32 -> tf32 hi/lo split (vectorized) ----------------
__global__ void split_kernel(const float4* __restrict__ in,
                             uint4* __restrict__ h, uint4* __restrict__ l, int n4) {
    int i = blockIdx.x * blockDim.x + threadIdx.x;
    if (i >= n4) return;
    float4 v = in[i];
    uint4 H, L;
    sp(v.x, H.x, L.x);
    sp(v.y, H.y, L.y);
    sp(v.z, H.z, L.z);
    sp(v.w, H.w, L.w);
    h[i] = H;
    l[i] = L;
}

// ---------------- RoPE tables (double precision to match numpy f64) ----------------
__global__ void rope_init_kernel() {
    int idx = blockIdx.x * blockDim.x + threadIdx.x;
    if (idx >= Sn * HD) return;
    int s = idx >> 6;
    int j = idx & 63;
    int jj = j & 31;
    double inv = pow(10000.0, -((double)(2 * jj)) / 64.0);
    double ang = (double)s * inv;
    g_cos[idx] = (float)cos(ang);
    g_sin[idx] = (float)sin(ang);
}

// ---------------- embedding gather (+ hi/lo) ----------------
__global__ void embed_kernel(const int* __restrict__ ids, const float* __restrict__ table,
                             float* __restrict__ out,
                             uint32_t* __restrict__ oh, uint32_t* __restrict__ ol) {
    int idx = blockIdx.x * blockDim.x + threadIdx.x;
    int t = idx >> 10;
    int d = idx & 1023;
    float v = table[(long long)ids[t] * Dm + d];
    out[idx] = v;
    uint32_t h, l;
    sp(v, h, l);
    oh[idx] = h;
    ol[idx] = l;
}

// ---------------- fp32 scalar SGEMM (tiny gate GEMM, N=8; exact routing) ----------------
__global__ void sgemm_kernel(const float* __restrict__ A, const float* __restrict__ W,
                             const float* __restrict__ bias, float* __restrict__ C,
                             int M, int N, int K) {
    const int tid = threadIdx.x;
    const int bm = blockIdx.y * 64, bn = blockIdx.x * 64;
    __shared__ float As[16][68];
    __shared__ float Ws[16][68];
    float acc[4][4] = {};
    const int ty = tid >> 4, tx = tid & 15;
    for (int k0 = 0; k0 < K; k0 += 16) {
#pragma unroll
        for (int i = 0; i < 4; i++) {
            int e = tid + i * 256;
            int r = e >> 4, kk = e & 15;
            int gr = bm + r, gk = k0 + kk;
            As[kk][r] = (gr < M && gk < K) ? A[(long long)gr * K + gk] : 0.f;
        }
#pragma unroll
        for (int i = 0; i < 4; i++) {
            int e = tid + i * 256;
            int kk = e >> 6, c = e & 63;
            int gk = k0 + kk, gc = bn + c;
            Ws[kk][c] = (gk < K && gc < N) ? W[(long long)gk * N + gc] : 0.f;
        }
        __syncthreads();
#pragma unroll
        for (int kk = 0; kk < 16; kk++) {
            float4 a4 = *(const float4*)&As[kk][ty * 4];
            float4 b4 = *(const float4*)&Ws[kk][tx * 4];
            float av[4] = {a4.x, a4.y, a4.z, a4.w};
            float bv[4] = {b4.x, b4.y, b4.z, b4.w};
#pragma unroll
            for (int i = 0; i < 4; i++)
#pragma unroll
                for (int j = 0; j < 4; j++) acc[i][j] += av[i] * bv[j];
        }
        __syncthreads();
    }
#pragma unroll
    for (int i = 0; i < 4; i++) {
        int r = bm + ty * 4 + i;
        if (r >= M) continue;
#pragma unroll
        for (int j = 0; j < 4; j++) {
            int c = bn + tx * 4 + j;
            if (c >= N) continue;
            C[(long long)r * N + c] = acc[i][j] + (bias ? bias[c] : 0.f);
        }
    }
}

// ---------------- RoPE + [tok,D] -> [b,h,s,hd] permute (hi/lo out) ----------------
__global__ void rope_perm_kernel(const float* __restrict__ lin,
                                 uint32_t* __restrict__ oh, uint32_t* __restrict__ ol,
                                 int do_rope) {
    int idx = blockIdx.x * blockDim.x + threadIdx.x;
    int t = idx >> 10;
    int col = idx & 1023;
    int b = t >> 9;
    int s = t & 511;
    int h = col >> 6;
    int d = col & 63;
    float v = lin[idx];
    float o = v;
    if (do_rope) {
        float other = (d < 32) ? -lin[idx + 32] : lin[idx - 32];
        o = v * g_cos[s * 64 + d] + other * g_sin[s * 64 + d];
    }
    long long oi = ((long long)(b * Hn + h) * Sn + s) * HD + d;
    uint32_t hh, ll;
    sp(o, hh, ll);
    oh[oi] = hh;
    ol[oi] = ll;
}

// ---------------- [b,h,s,hd] -> [tok,D] permute (hi/lo out) ----------------
__global__ void perm_back_kernel(const float* __restrict__ att,
                                 uint32_t* __restrict__ oh, uint32_t* __restrict__ ol) {
    int idx = blockIdx.x * blockDim.x + threadIdx.x;
    int d = idx & 63;
    int s = (idx >> 6) & 511;
    int h = (idx >> 15) & 15;
    int b = idx >> 19;
    long long oi = (long long)(b * Sn + s) * Dm + h * HD + d;
    uint32_t hh, ll;
    sp(att[idx], hh, ll);
    oh[oi] = hh;
    ol[oi] = ll;
}

// ---------------- row softmax with causal option (hi/lo out) ----------------
__global__ void softmax_rows_kernel(const float* __restrict__ sc,
                                    uint32_t* __restrict__ oh, uint32_t* __restrict__ ol,
                                    int causal) {
    int row = blockIdx.x;
    long long base = ((long long)blockIdx.y * Sn + row) * Sn;
    int tid = threadIdx.x;
    float v0 = sc[base + tid];
    float v1 = sc[base + tid + 256];
    if (causal) {
        if (tid > row) v0 = -1e9f;
        if (tid + 256 > row) v1 = -1e9f;
    }
    __shared__ float red[256];
    float m = fmaxf(v0, v1);
    red[tid] = m;
    __syncthreads();
    for (int s = 128; s > 0; s >>= 1) {
        if (tid < s) red[tid] = fmaxf(red[tid], red[tid + s]);
        __syncthreads();
    }
    m = red[0];
    __syncthreads();
    float e0 = expf(v0 - m), e1 = expf(v1 - m);
    red[tid] = e0 + e1;
    __syncthreads();
    for (int s = 128; s > 0; s >>= 1) {
        if (tid < s) red[tid] += red[tid + s];
        __syncthreads();
    }
    float inv = 1.f / red[0];
    uint32_t h, l;
    sp(e0 * inv, h, l);
    oh[base + tid] = h;
    ol[base + tid] = l;
    sp(e1 * inv, h, l);
    oh[base + tid + 256] = h;
    ol[base + tid + 256] = l;
}

// ---------------- fused residual add(+add2) + layernorm (+ hi/lo) ----------------
__global__ void add_ln_kernel(const float* __restrict__ x, const float* __restrict__ a,
                              const float* __restrict__ a2,
                              const float* __restrict__ g, const float* __restrict__ b,
                              float* __restrict__ out,
                              uint32_t* __restrict__ oh, uint32_t* __restrict__ ol) {
    int t = blockIdx.x;
    int tid = threadIdx.x;
    long long base = (long long)t * Dm;
    float v[4];
#pragma unroll
    for (int i = 0; i < 4; i++) {
        int c = tid + i * 256;
        float s = x[base + c] + a[base + c];
        if (a2) s += a2[base + c];
        v[i] = s;
    }
    __shared__ float red[256];
    red[tid] = v[0] + v[1] + v[2] + v[3];
    __syncthreads();
    for (int k = 128; k > 0; k >>= 1) {
        if (tid < k) red[tid] += red[tid + k];
        __syncthreads();
    }
    float mu = red[0] * (1.f / Dm);
    __syncthreads();
    float q = 0.f;
#pragma unroll
    for (int i = 0; i < 4; i++) { float d = v[i] - mu; q += d * d; }
    red[tid] = q;
    __syncthreads();
    for (int k = 128; k > 0; k >>= 1) {
        if (tid < k) red[tid] += red[tid + k];
        __syncthreads();
    }
    float var = red[0] * (1.f / Dm);
    float inv = rsqrtf(var + 1e-5f);
#pragma unroll
    for (int i = 0; i < 4; i++) {
        int c = tid + i * 256;
        float o = (v[i] - mu) * inv * g[c] + b[c];
        out[base + c] = o;
        uint32_t h, l;
        sp(o, h, l);
        oh[base + c] = h;
        ol[base + c] = l;
    }
}

// ---------------- MoE gating ----------------
__global__ void zero_cnt_kernel(int* c) { if (threadIdx.x < En) c[threadIdx.x] = 0; }

__global__ void gate_route_kernel(const float* __restrict__ logits, float* __restrict__ topw,
                                  int* __restrict__ list, int* __restrict__ cnt) {
    int t = blockIdx.x * blockDim.x + threadIdx.x;
    if (t >= TOK) return;
    float p[En];
    float m = -1e30f;
#pragma unroll
    for (int e = 0; e < En; e++) { p[e] = logits[t * En + e]; m = fmaxf(m, p[e]); }
    float s = 0.f;
#pragma unroll
    for (int e = 0; e < En; e++) { p[e] = expf(p[e] - m); s += p[e]; }
    float invs = 1.f / s;
#pragma unroll
    for (int e = 0; e < En; e++) p[e] *= invs;
    int i0 = 0;
#pragma unroll
    for (int e = 1; e < En; e++) if (p[e] > p[i0]) i0 = e;
    int i1 = (i0 == 0) ? 1 : 0;
#pragma unroll
    for (int e = 0; e < En; e++) if (e != i0 && p[e] > p[i1]) i1 = e;
    float s2 = p[i0] + p[i1];
    topw[t * 2 + 0] = p[i0] / s2;
    topw[t * 2 + 1] = p[i1] / s2;
    int pos = atomicAdd(&cnt[i0], 1);
    list[i0 * TOK + pos] = t * 2 + 0;
    pos = atomicAdd(&cnt[i1], 1);
    list[i1 * TOK + pos] = t * 2 + 1;
}

// ================= host orchestration =================
struct DevPtrs {
    float *x, *y, *lin0, *lin1, *lin2, *sc, *att, *proj, *moe0, *moe1, *gate, *topw;
    uint32_t *xh, *xl, *yh, *yl, *qh, *ql, *kh, *kl, *vh, *vl;
    uint32_t *sch, *scl, *atth, *attl, *h1h, *h1l, *wsh, *wsl;
    int *list, *cnt;
};

static void split_w(const float* w, uint32_t* h, uint32_t* l, long long n) {
    int n4 = (int)(n / 4);
    split_kernel<<<(n4 + 255) / 256, 256>>>((const float4*)w, (uint4*)h, (uint4*)l, n4);
}

static void hgemm(const uint32_t* Ah, const uint32_t* Al,
                  const uint32_t* Bh, const uint32_t* Bl,
                  const float* bias, float* C,
                  int M, int N, int K, float alpha = 1.f, int batch = 1,
                  long long sA = 0, long long sB = 0, long long sC = 0) {
    dim3 g((N + 127) / 128, M / 128, batch);
    mma_gemm_hl<0><<<g, 256, SMEM0_BYTES>>>(Ah, Al, Bh, Bl, bias, C, M, N, K, 0, alpha,
                                            sA, sB, sC);
}

static void hgemm_nt(const uint32_t* Ah, const uint32_t* Al,
                     const uint32_t* Bh, const uint32_t* Bl, float* C,
                     int M, int N, int K, float alpha, int batch,
                     long long sA, long long sB, long long sC) {
    dim3 g((N + 127) / 128, M / 128, batch);
    mma_gemm_hl<1><<<g, 256, SMEM1_BYTES>>>(Ah, Al, Bh, Bl, nullptr, C, M, N, K, 0, alpha,
                                            sA, sB, sC);
}

static void run_mha(DevPtrs& P, float* xio, uint32_t* xh, uint32_t* xl,
                    const uint32_t* kvh, const uint32_t* kvl,
                    const float* wqkv, const float* bqkv,
                    const float* wo, const float* bo,
                    const float* lng, const float* lnb, int causal) {
    // split qkv weights (contiguous 3*Dm*Dm) into scratch
    split_w(wqkv, P.wsh, P.wsl, 3LL * Dm * Dm);
    hgemm(xh,  xl,  P.wsh,               P.wsl,               bqkv,          P.lin0, TOK, Dm, Dm);
    hgemm(kvh, kvl, P.wsh + Dm * Dm,     P.wsl + Dm * Dm,     bqkv + Dm,     P.lin1, TOK, Dm, Dm);
    hgemm(kvh, kvl, P.wsh + 2 * Dm * Dm, P.wsl + 2 * Dm * Dm, bqkv + 2 * Dm, P.lin2, TOK, Dm, Dm);
    int nb = (TOK * Dm) / 256;
    rope_perm_kernel<<<nb, 256>>>(P.lin0, P.qh, P.ql, 1);
    rope_perm_kernel<<<nb, 256>>>(P.lin1, P.kh, P.kl, 1);
    rope_perm_kernel<<<nb, 256>>>(P.lin2, P.vh, P.vl, 0);
    hgemm_nt(P.qh, P.ql, P.kh, P.kl, P.sc, Sn, Sn, HD, 0.125f, Bn * Hn,
             (long long)Sn * HD, (long long)Sn * HD, (long long)Sn * Sn);
    softmax_rows_kernel<<<dim3(Sn, Bn * Hn), 256>>>(P.sc, P.sch, P.scl, causal);
    hgemm(P.sch, P.scl, P.vh, P.vl, nullptr, P.att, Sn, HD, Sn, 1.f, Bn * Hn,
          (long long)Sn * Sn, (long long)Sn * HD, (long long)Sn * HD);
    perm_back_kernel<<<nb, 256>>>(P.att, P.atth, P.attl);
    split_w(wo, P.wsh, P.wsl, (long long)Dm * Dm);
    hgemm(P.atth, P.attl, P.wsh, P.wsl, bo, P.proj, TOK, Dm, Dm);
    add_ln_kernel<<<TOK, 256>>>(xio, P.proj, nullptr, lng, lnb, xio, xh, xl);
}

static void run_moe(DevPtrs& P, float* xio, uint32_t* xh, uint32_t* xl,
                    const float* gw, const float* gb,
                    const float* w1, const float* b1, const float* w2, const float* b2,
                    const float* lng, const float* lnb) {
    sgemm_kernel<<<dim3(1, TOK / 64), 256>>>(xio, gw, gb, P.gate, TOK, En, Dm);
    zero_cnt_kernel<<<1, 32>>>(P.cnt);
    gate_route_kernel<<<TOK / 256, 256>>>(P.gate, P.topw, P.list, P.cnt);
    split_w(w1, P.wsh, P.wsl, (long long)En * Dm * FF);
    moe_mma1_hl<<<dim3(FF / 128, TOK / 128, En), 256, SMEM0_BYTES>>>(
        xh, xl, P.wsh, P.wsl, b1, P.h1h, P.h1l, P.list, P.cnt);
    split_w(w2, P.wsh, P.wsl, (long long)En * FF * Dm);
    moe_mma2_hl<<<dim3(Dm / 128, TOK / 128, En), 256, SMEM0_BYTES>>>(
        P.h1h, P.h1l, P.wsh, P.wsl, b2, P.moe0, P.moe1, P.topw, P.list, P.cnt);
    add_ln_kernel<<<TOK, 256>>>(xio, P.moe0, P.moe1, lng, lnb, xio, xh, xl);
}

extern "C" void kernel_launch(void* const* d_in, const int* in_sizes, int n_in,
                              void* d_out, int out_size) {
    (void)in_sizes; (void)n_in; (void)out_size;
    const int*   src           = (const int*)  d_in[0];
    const int*   tgt           = (const int*)  d_in[1];
    const float* emb_src       = (const float*)d_in[2];
    const float* emb_tgt       = (const float*)d_in[3];
    const float* enc_wqkv      = (const float*)d_in[4];
    const float* enc_bqkv      = (const float*)d_in[5];
    const float* enc_wo        = (const float*)d_in[6];
    const float* enc_bo        = (const float*)d_in[7];
    const float* enc_gate_w    = (const float*)d_in[8];
    const float* enc_gate_b    = (const float*)d_in[9];
    const float* enc_w1        = (const float*)d_in[10];
    const float* enc_b1        = (const float*)d_in[11];
    const float* enc_w2        = (const float*)d_in[12];
    const float* enc_b2        = (const float*)d_in[13];
    const float* enc_ln        = (const float*)d_in[14];
    const float* dec_self_wqkv = (const float*)d_in[15];
    const float* dec_self_bqkv = (const float*)d_in[16];
    const float* dec_self_wo   = (const float*)d_in[17];
    const float* dec_self_bo   = (const float*)d_in[18];
    const float* dec_cross_wqkv= (const float*)d_in[19];
    const float* dec_cross_bqkv= (const float*)d_in[20];
    const float* dec_cross_wo  = (const float*)d_in[21];
    const float* dec_cross_bo  = (const float*)d_in[22];
    const float* dec_gate_w    = (const float*)d_in[23];
    const float* dec_gate_b    = (const float*)d_in[24];
    const float* dec_w1        = (const float*)d_in[25];
    const float* dec_b1        = (const float*)d_in[26];
    const float* dec_w2        = (const float*)d_in[27];
    const float* dec_b2        = (const float*)d_in[28];
    const float* dec_ln        = (const float*)d_in[29];
    const float* final_w       = (const float*)d_in[30];
    const float* final_b       = (const float*)d_in[31];
    float* out = (float*)d_out;

    // raise dynamic smem limits (host-side attribute, not a stream op)
    cudaFuncSetAttribute(mma_gemm_hl<0>, cudaFuncAttributeMaxDynamicSharedMemorySize, SMEM0_BYTES);
    cudaFuncSetAttribute(mma_gemm_hl<1>, cudaFuncAttributeMaxDynamicSharedMemorySize, SMEM1_BYTES);
    cudaFuncSetAttribute(moe_mma1_hl,    cudaFuncAttributeMaxDynamicSharedMemorySize, SMEM0_BYTES);
    cudaFuncSetAttribute(moe_mma2_hl,    cudaFuncAttributeMaxDynamicSharedMemorySize, SMEM0_BYTES);

    DevPtrs P;
    cudaGetSymbolAddress((void**)&P.x, g_x);
    cudaGetSymbolAddress((void**)&P.y, g_y);
    cudaGetSymbolAddress((void**)&P.xh, g_xh);
    cudaGetSymbolAddress((void**)&P.xl, g_xl);
    cudaGetSymbolAddress((void**)&P.yh, g_yh);
    cudaGetSymbolAddress((void**)&P.yl, g_yl);
    cudaGetSymbolAddress((void**)&P.lin0, g_lin0);
    cudaGetSymbolAddress((void**)&P.lin1, g_lin1);
    cudaGetSymbolAddress((void**)&P.lin2, g_lin2);
    cudaGetSymbolAddress((void**)&P.qh, g_qh);
    cudaGetSymbolAddress((void**)&P.ql, g_ql);
    cudaGetSymbolAddress((void**)&P.kh, g_kh);
    cudaGetSymbolAddress((void**)&P.kl, g_kl);
    cudaGetSymbolAddress((void**)&P.vh, g_vh);
    cudaGetSymbolAddress((void**)&P.vl, g_vl);
    cudaGetSymbolAddress((void**)&P.sc, g_sc);
    cudaGetSymbolAddress((void**)&P.sch, g_sch);
    cudaGetSymbolAddress((void**)&P.scl, g_scl);
    cudaGetSymbolAddress((void**)&P.att, g_att);
    cudaGetSymbolAddress((void**)&P.atth, g_atth);
    cudaGetSymbolAddress((void**)&P.attl, g_attl);
    cudaGetSymbolAddress((void**)&P.proj, g_proj);
    cudaGetSymbolAddress((void**)&P.h1h, g_h1h);
    cudaGetSymbolAddress((void**)&P.h1l, g_h1l);
    cudaGetSymbolAddress((void**)&P.moe0, g_moe0);
    cudaGetSymbolAddress((void**)&P.moe1, g_moe1);
    cudaGetSymbolAddress((void**)&P.gate, g_gate);
    cudaGetSymbolAddress((void**)&P.topw, g_topw);
    cudaGetSymbolAddress((void**)&P.list, g_list);
    cudaGetSymbolAddress((void**)&P.cnt, g_cnt);
    cudaGetSymbolAddress((void**)&P.wsh, g_wsh);
    cudaGetSymbolAddress((void**)&P.wsl, g_wsl);

    rope_init_kernel<<<(Sn * HD) / 256, 256>>>();

    // ---------- encoder ----------
    embed_kernel<<<(TOK * Dm) / 256, 256>>>(src, emb_src, P.x, P.xh, P.xl);
    for (int l = 0; l < Ln; l++) {
        run_mha(P, P.x, P.xh, P.xl, P.xh, P.xl,
                enc_wqkv + (long long)l * 3 * Dm * Dm, enc_bqkv + l * 3 * Dm,
                enc_wo + (long long)l * Dm * Dm, enc_bo + l * Dm,
                enc_ln + ((l * 2 + 0) * 2 + 0) * Dm, enc_ln + ((l * 2 + 0) * 2 + 1) * Dm, 0);
        run_moe(P, P.x, P.xh, P.xl,
                enc_gate_w + l * Dm * En, enc_gate_b + l * En,
                enc_w1 + (long long)l * En * Dm * FF, enc_b1 + l * En * FF,
                enc_w2 + (long long)l * En * FF * Dm, enc_b2 + l * En * Dm,
                enc_ln + ((l * 2 + 1) * 2 + 0) * Dm, enc_ln + ((l * 2 + 1) * 2 + 1) * Dm);
    }

    // ---------- decoder ----------
    embed_kernel<<<(TOK * Dm) / 256, 256>>>(tgt, emb_tgt, P.y, P.yh, P.yl);
    for (int l = 0; l < Ln; l++) {
        run_mha(P, P.y, P.yh, P.yl, P.yh, P.yl,
                dec_self_wqkv + (long long)l * 3 * Dm * Dm, dec_self_bqkv + l * 3 * Dm,
                dec_self_wo + (long long)l * Dm * Dm, dec_self_bo + l * Dm,
                dec_ln + ((l * 3 + 0) * 2 + 0) * Dm, dec_ln + ((l * 3 + 0) * 2 + 1) * Dm, 1);
        run_mha(P, P.y, P.yh, P.yl, P.xh, P.xl,
                dec_cross_wqkv + (long long)l * 3 * Dm * Dm, dec_cross_bqkv + l * 3 * Dm,
                dec_cross_wo + (long long)l * Dm * Dm, dec_cross_bo + l * Dm,
                dec_ln + ((l * 3 + 1) * 2 + 0) * Dm, dec_ln + ((l * 3 + 1) * 2 + 1) * Dm, 0);
        run_moe(P, P.y, P.yh, P.yl,
                dec_gate_w + l * Dm * En, dec_gate_b + l * En,
                dec_w1 + (long long)l * En * Dm * FF, dec_b1 + l * En * FF,
                dec_w2 + (long long)l * En * FF * Dm, dec_b2 + l * En * Dm,
                dec_ln + ((l * 3 + 2) * 2 + 0) * Dm, dec_ln + ((l * 3 + 2) * 2 + 1) * Dm);
    }

    // ---------- final projection ----------
    split_w(final_w, P.wsh, P.wsl, (long long)Dm * VT);
    hgemm(P.yh, P.yl, P.wsh, P.wsl, final_b, out, TOK, VT, Dm);
}